// round 1
// baseline (speedup 1.0000x reference)
#include <cuda_runtime.h>

#define NS 512      // sequence length N
#define DD 64       // feature dim d
#define NB 64       // batch B
#define GT 128      // DP tiles per side = NS/4
#define INFV 1e10f  // matches reference INF_REPLACE semantics

// 64 MB scratch for the distance matrix (static __device__ — allocation-free).
__device__ float g_D[(size_t)NB * NS * NS];

// ---------------------------------------------------------------------------
// Packed f32x2 FMA (Blackwell): d.lo += a.lo*b.lo ; d.hi += a.hi*b.hi
// ---------------------------------------------------------------------------
__device__ __forceinline__ void fma2(unsigned long long& d,
                                     unsigned long long a,
                                     unsigned long long b) {
    asm("fma.rn.f32x2 %0, %1, %2, %0;" : "+l"(d) : "l"(a), "l"(b));
}

// ---------------------------------------------------------------------------
// Stage 1: D[b,i,j] = sqrt(max(0, |x_i|^2 + |y_j|^2 - 2 x_i.y_j))
// One CTA computes a 64x64 tile of D for one batch. 256 threads, each 4x4 out.
// SMEM tiles stored row-major [row][k] with float4-granular XOR swizzle
// (k4 ^ (row & 15)) -> conflict-free LDS.128 across 16 distinct rows.
// ---------------------------------------------------------------------------
__global__ void __launch_bounds__(256, 1)
cdist_kernel(const float* __restrict__ X, const float* __restrict__ Y) {
    __shared__ float Xs[64 * 64];
    __shared__ float Ys[64 * 64];
    __shared__ float xn[64], yn[64];

    const int b  = blockIdx.z;
    const int i0 = blockIdx.y * 64;
    const int j0 = blockIdx.x * 64;
    const int tid = threadIdx.y * 16 + threadIdx.x;

    const float* Xg = X + ((size_t)b * NS + i0) * DD;
    const float* Yg = Y + ((size_t)b * NS + j0) * DD;

    float4* Xs4 = reinterpret_cast<float4*>(Xs);
    float4* Ys4 = reinterpret_cast<float4*>(Ys);

    // Load both 64x64 tiles (coalesced float4 LDG, swizzled STS.128).
#pragma unroll
    for (int t = 0; t < 4; ++t) {
        int lin = t * 256 + tid;     // float4 index 0..1023
        int row = lin >> 4;          // 0..63
        int k4  = lin & 15;          // 0..15
        int sw  = k4 ^ (row & 15);
        Xs4[row * 16 + sw] = *reinterpret_cast<const float4*>(Xg + row * DD + k4 * 4);
        Ys4[row * 16 + sw] = *reinterpret_cast<const float4*>(Yg + row * DD + k4 * 4);
    }
    __syncthreads();

    // Row norms (one-time, 128 threads).
    if (tid < 128) {
        int r = tid & 63;
        const float4* P = (tid < 64) ? reinterpret_cast<const float4*>(Xs)
                                     : reinterpret_cast<const float4*>(Ys);
        float s = 0.0f;
#pragma unroll
        for (int k4 = 0; k4 < 16; ++k4) {
            float4 v = P[r * 16 + (k4 ^ (r & 15))];
            s += v.x * v.x + v.y * v.y + v.z * v.z + v.w * v.w;
        }
        if (tid < 64) xn[r] = s; else yn[r] = s;
    }
    __syncthreads();

    const int tx = threadIdx.x, ty = threadIdx.y;

    // acc[r][c] packs two fp32 partial sums (even-k / odd-k lanes).
    unsigned long long acc[4][4];
#pragma unroll
    for (int r = 0; r < 4; ++r)
#pragma unroll
        for (int c = 0; c < 4; ++c) acc[r][c] = 0ull;

    const ulonglong2* Xs2 = reinterpret_cast<const ulonglong2*>(Xs);
    const ulonglong2* Ys2 = reinterpret_cast<const ulonglong2*>(Ys);

#pragma unroll
    for (int k4 = 0; k4 < 16; ++k4) {
        ulonglong2 av[4], bv[4];
#pragma unroll
        for (int r = 0; r < 4; ++r) {
            int i = ty + 16 * r;
            av[r] = Xs2[i * 16 + (k4 ^ (i & 15))];
        }
#pragma unroll
        for (int c = 0; c < 4; ++c) {
            int j = tx + 16 * c;
            bv[c] = Ys2[j * 16 + (k4 ^ (j & 15))];
        }
#pragma unroll
        for (int r = 0; r < 4; ++r)
#pragma unroll
            for (int c = 0; c < 4; ++c) {
                fma2(acc[r][c], av[r].x, bv[c].x);
                fma2(acc[r][c], av[r].y, bv[c].y);
            }
    }

    float* Dout = g_D + (size_t)b * NS * NS;
#pragma unroll
    for (int r = 0; r < 4; ++r) {
        int i = ty + 16 * r;
#pragma unroll
        for (int c = 0; c < 4; ++c) {
            int j = tx + 16 * c;
            float lo = __uint_as_float((unsigned)(acc[r][c] & 0xffffffffull));
            float hi = __uint_as_float((unsigned)(acc[r][c] >> 32));
            float d2 = xn[i] + yn[j] - 2.0f * (lo + hi);
            Dout[(size_t)(i0 + i) * NS + (j0 + j)] = sqrtf(fmaxf(d2, 0.0f));
        }
    }
}

// ---------------------------------------------------------------------------
// Stage 2: soft-DTW DP. One CTA per batch, 128 threads, thread ti owns tile
// row ti (4 DP rows). Wavefront over 255 tile anti-diagonals; frontiers are
// parity double-buffered so a single __syncthreads per diagonal suffices.
// ---------------------------------------------------------------------------
__device__ __forceinline__ float softmin3(float a, float b, float c) {
    float m = fminf(a, fminf(b, c));
    float s = __expf(m - a) + __expf(m - b) + __expf(m - c);
    return m - __logf(s);
}

__device__ __forceinline__ void tile4(const float4 (&dt)[4],
                                      float (&prev)[5],
                                      const float (&left)[4],
                                      float (&right)[4]) {
#pragma unroll
    for (int a = 0; a < 4; ++a) {
        const float dd[4] = {dt[a].x, dt[a].y, dt[a].z, dt[a].w};
        float carry = prev[0];
        prev[0] = left[a];
#pragma unroll
        for (int q = 1; q <= 4; ++q) {
            float dgv = carry;       // old prev[q-1] (diag)
            carry = prev[q];         // old prev[q]   (up)
            prev[q] = dd[q - 1] + softmin3(dgv, carry, prev[q - 1]);
        }
        right[a] = prev[4];
    }
}

__global__ void __launch_bounds__(128, 1)
dp_kernel(float* __restrict__ out) {
    const int b = blockIdx.x;
    const float* Db = g_D + (size_t)b * NS * NS;

    __shared__ float rowF[2][NS + 4];     // bottom-row frontier per parity
    __shared__ float colF[2][NS + 4];     // right-col frontier per parity
    __shared__ float cornerS[2][GT + 2];  // saved diagonal corners per parity

    const int ti = threadIdx.x;           // tile row 0..127
    const int i0 = ti * 4;

    // Prefetch D tile (ti, 0).
    float4 bufA[4], bufB[4];
#pragma unroll
    for (int a = 0; a < 4; ++a)
        bufA[a] = *reinterpret_cast<const float4*>(Db + (size_t)(i0 + a) * NS);

    __syncthreads();

    for (int kd = 0; kd < 2 * GT - 1; ++kd) {
        const int tj  = kd - ti;
        const bool act = (tj >= 0) && (tj < GT);
        const int wb = kd & 1;       // write-parity this diagonal
        const int rb = wb ^ 1;       // read-parity (written on diagonal kd-1)
        const int j0 = tj * 4;

        float top[5], left[4];
        if (act) {
            if (ti == 0) {
                top[0] = (tj == 0) ? 0.0f : INFV;
                top[1] = top[2] = top[3] = top[4] = INFV;
            } else {
                top[0] = (tj == 0) ? INFV : cornerS[rb][tj];
#pragma unroll
                for (int q = 1; q <= 4; ++q) top[q] = rowF[rb][j0 + q];
            }
            if (tj == 0) {
                left[0] = left[1] = left[2] = left[3] = INFV;
            } else {
#pragma unroll
                for (int a = 0; a < 4; ++a) left[a] = colF[rb][i0 + 1 + a];
            }

            float prev[5], right[4];
#pragma unroll
            for (int q = 0; q <= 4; ++q) prev[q] = top[q];

            // Double-buffered D: issue next tile's loads before the MUFU chain.
            if ((tj & 1) == 0) {
                if (tj + 1 < GT) {
#pragma unroll
                    for (int a = 0; a < 4; ++a)
                        bufB[a] = *reinterpret_cast<const float4*>(
                            Db + (size_t)(i0 + a) * NS + (j0 + 4));
                }
                tile4(bufA, prev, left, right);
            } else {
                if (tj + 1 < GT) {
#pragma unroll
                    for (int a = 0; a < 4; ++a)
                        bufA[a] = *reinterpret_cast<const float4*>(
                            Db + (size_t)(i0 + a) * NS + (j0 + 4));
                }
                tile4(bufB, prev, left, right);
            }

            // Publish frontiers for diagonal kd+1 (disjoint parity from reads).
#pragma unroll
            for (int q = 1; q <= 4; ++q) rowF[wb][j0 + q] = prev[q];
#pragma unroll
            for (int a = 0; a < 4; ++a) colF[wb][i0 + 1 + a] = right[a];
            cornerS[wb][tj + 1] = top[4];   // old R[i0][j0+4] = corner for (ti, tj+1)
        }
        __syncthreads();
    }

    // Final diagonal (kd = 254) wrote with parity 0: R[N][N] = rowF[0][N].
    if (ti == 0) out[b] = rowF[0][NS];
}

// ---------------------------------------------------------------------------
extern "C" void kernel_launch(void* const* d_in, const int* in_sizes, int n_in,
                              void* d_out, int out_size) {
    (void)in_sizes; (void)n_in; (void)out_size;
    const float* X = (const float*)d_in[0];
    const float* Y = (const float*)d_in[1];
    float* out = (float*)d_out;

    dim3 g1(NS / 64, NS / 64, NB);   // (8, 8, 64)
    dim3 b1(16, 16);
    cdist_kernel<<<g1, b1>>>(X, Y);

    dp_kernel<<<NB, 128>>>(out);
}

// round 3
// speedup vs baseline: 1.6585x; 1.6585x over previous
#include <cuda_runtime.h>

#define NS 512      // sequence length N
#define DD 64       // feature dim d
#define NB 64       // batch B
#define GT 128      // DP tiles per side = NS/4
#define C2_NEG (-0x40000000)

// 64 MB scratch: E[b,i,j] = exp(-||x_i - y_j||)  (static __device__ — allocation-free)
__device__ float g_E[(size_t)NB * NS * NS];

// ---------------------------------------------------------------------------
// Packed f32x2 FMA (Blackwell): d.lo += a.lo*b.lo ; d.hi += a.hi*b.hi
// ---------------------------------------------------------------------------
__device__ __forceinline__ void fma2(unsigned long long& d,
                                     unsigned long long a,
                                     unsigned long long b) {
    asm("fma.rn.f32x2 %0, %1, %2, %0;" : "+l"(d) : "l"(a), "l"(b));
}

// ---------------------------------------------------------------------------
// Stage 1: E[b,i,j] = exp(-sqrt(max(0, |x_i|^2 + |y_j|^2 - 2 x_i.y_j)))
// One CTA computes a 64x64 tile for one batch. 256 threads, each 4x4 outputs.
// ---------------------------------------------------------------------------
__global__ void __launch_bounds__(256, 1)
cdist_kernel(const float* __restrict__ X, const float* __restrict__ Y) {
    __shared__ float Xs[64 * 64];
    __shared__ float Ys[64 * 64];
    __shared__ float xn[64], yn[64];

    const int b  = blockIdx.z;
    const int i0 = blockIdx.y * 64;
    const int j0 = blockIdx.x * 64;
    const int tid = threadIdx.y * 16 + threadIdx.x;

    const float* Xg = X + ((size_t)b * NS + i0) * DD;
    const float* Yg = Y + ((size_t)b * NS + j0) * DD;

    float4* Xs4 = reinterpret_cast<float4*>(Xs);
    float4* Ys4 = reinterpret_cast<float4*>(Ys);

#pragma unroll
    for (int t = 0; t < 4; ++t) {
        int lin = t * 256 + tid;     // float4 index 0..1023
        int row = lin >> 4;          // 0..63
        int k4  = lin & 15;          // 0..15
        int sw  = k4 ^ (row & 15);
        Xs4[row * 16 + sw] = *reinterpret_cast<const float4*>(Xg + row * DD + k4 * 4);
        Ys4[row * 16 + sw] = *reinterpret_cast<const float4*>(Yg + row * DD + k4 * 4);
    }
    __syncthreads();

    if (tid < 128) {
        int r = tid & 63;
        const float4* P = (tid < 64) ? reinterpret_cast<const float4*>(Xs)
                                     : reinterpret_cast<const float4*>(Ys);
        float s = 0.0f;
#pragma unroll
        for (int k4 = 0; k4 < 16; ++k4) {
            float4 v = P[r * 16 + (k4 ^ (r & 15))];
            s += v.x * v.x + v.y * v.y + v.z * v.z + v.w * v.w;
        }
        if (tid < 64) xn[r] = s; else yn[r] = s;
    }
    __syncthreads();

    const int tx = threadIdx.x, ty = threadIdx.y;

    unsigned long long acc[4][4];
#pragma unroll
    for (int r = 0; r < 4; ++r)
#pragma unroll
        for (int c = 0; c < 4; ++c) acc[r][c] = 0ull;

    const ulonglong2* Xs2 = reinterpret_cast<const ulonglong2*>(Xs);
    const ulonglong2* Ys2 = reinterpret_cast<const ulonglong2*>(Ys);

#pragma unroll
    for (int k4 = 0; k4 < 16; ++k4) {
        ulonglong2 av[4], bv[4];
#pragma unroll
        for (int r = 0; r < 4; ++r) {
            int i = ty + 16 * r;
            av[r] = Xs2[i * 16 + (k4 ^ (i & 15))];
        }
#pragma unroll
        for (int c = 0; c < 4; ++c) {
            int j = tx + 16 * c;
            bv[c] = Ys2[j * 16 + (k4 ^ (j & 15))];
        }
#pragma unroll
        for (int r = 0; r < 4; ++r)
#pragma unroll
            for (int c = 0; c < 4; ++c) {
                fma2(acc[r][c], av[r].x, bv[c].x);
                fma2(acc[r][c], av[r].y, bv[c].y);
            }
    }

    float* Eout = g_E + (size_t)b * NS * NS;
#pragma unroll
    for (int r = 0; r < 4; ++r) {
        int i = ty + 16 * r;
#pragma unroll
        for (int c = 0; c < 4; ++c) {
            int j = tx + 16 * c;
            float lo = __uint_as_float((unsigned)(acc[r][c] & 0xffffffffull));
            float hi = __uint_as_float((unsigned)(acc[r][c] >> 32));
            float d2 = xn[i] + yn[j] - 2.0f * (lo + hi);
            float dist = sqrtf(fmaxf(d2, 0.0f));
            // exp(-dist) = exp2(-dist * log2(e)) — single EX2
            Eout[(size_t)(i0 + i) * NS + (j0 + j)] =
                exp2f(-1.4426950408889634f * dist);
        }
    }
}

// ---------------------------------------------------------------------------
// Stage 2: soft-DTW in the weight domain with binary scaling.
//   W[i,j] = exp(-d_ij) * (W[i-1,j-1] + W[i-1,j] + W[i,j-1]),  answer = -ln W[N,N]
// Each frontier group (top row slice / left col slice / corner) carries its
// own power-of-two scale c2 that tracks its true magnitude; groups are
// aligned to the max scale on consumption and outputs are renormalized by
// exponent extraction — pure ALU, zero MUFU in the recurrence.
// ---------------------------------------------------------------------------
__device__ __forceinline__ float exp2i_neg(int e) {
    // 2^e for e <= 0, flushing to 0 below 2^-126
    return (e >= -126) ? __int_as_float((e + 127) << 23) : 0.0f;
}

__device__ __forceinline__ int fexp(float m) {
    return ((__float_as_int(m) >> 23) & 0xff) - 127;
}

__device__ __forceinline__ void tile4w(const float4 (&dt)[4],
                                       float (&prev)[5],
                                       const float (&lE)[4],
                                       float (&right)[4]) {
#pragma unroll
    for (int a = 0; a < 4; ++a) {
        const float dd0 = dt[a].x, dd1 = dt[a].y, dd2 = dt[a].z, dd3 = dt[a].w;
        float carry = prev[0];          // diag (old prev[q-1])
        prev[0] = lE[a];                // new left input
        float s;
        s = (carry + prev[1]) + prev[0]; carry = prev[1]; prev[1] = dd0 * s;
        s = (carry + prev[2]) + prev[1]; carry = prev[2]; prev[2] = dd1 * s;
        s = (carry + prev[3]) + prev[2]; carry = prev[3]; prev[3] = dd2 * s;
        s = (carry + prev[4]) + prev[3];                  prev[4] = dd3 * s;
        right[a] = prev[4];
    }
}

__global__ void __launch_bounds__(128, 1)
dp_kernel(float* __restrict__ out) {
    const int b = blockIdx.x;
    const float* Eb = g_E + (size_t)b * NS * NS;

    __shared__ __align__(16) float rowE[2][NS];   // bottom-row frontier (mantissas)
    __shared__ int rowC2[2][GT];                  // per-tile row-group exponent

    const int ti = threadIdx.x;           // tile row 0..127
    const int i0 = ti * 4;

    // Prefetch E tile (ti, 0).
    float4 bufA[4], bufB[4];
#pragma unroll
    for (int a = 0; a < 4; ++a)
        bufA[a] = *reinterpret_cast<const float4*>(Eb + (size_t)(i0 + a) * NS);

    // Register-resident frontiers: left column + diagonal corner.
    float leftE[4] = {0.0f, 0.0f, 0.0f, 0.0f};   // R[i][-1] = inf -> W = 0
    int   leftC2 = C2_NEG;
    float cornE  = (ti == 0) ? 1.0f : 0.0f;       // R[-1][-1]: 0 for row 0 else inf
    int   cornC2 = (ti == 0) ? 0 : C2_NEG;

    __syncthreads();

    for (int kd = 0; kd < 2 * GT - 1; ++kd) {
        const int tj = kd - ti;
        const int wb = kd & 1;       // write parity
        const int rb = wb ^ 1;       // read parity
        if (tj >= 0 && tj < GT) {
            const int j0 = tj * 4;

            // Gather top frontier (DP boundary row is all-inf -> W = 0).
            float topE0, topE1, topE2, topE3; int topC2v;
            if (ti == 0) {
                topE0 = topE1 = topE2 = topE3 = 0.0f;
                topC2v = C2_NEG;
            } else {
                float4 t = *reinterpret_cast<const float4*>(&rowE[rb][j0]);
                topE0 = t.x; topE1 = t.y; topE2 = t.z; topE3 = t.w;
                topC2v = rowC2[rb][tj];
            }

            // Align the three incoming scale groups to the max exponent.
            int c2 = max(max(topC2v, cornC2), leftC2);
            const float ft = exp2i_neg(topC2v - c2);
            const float fc = exp2i_neg(cornC2 - c2);
            const float fl = exp2i_neg(leftC2 - c2);

            float prev[5];
            prev[0] = cornE * fc;
            prev[1] = topE0 * ft; prev[2] = topE1 * ft;
            prev[3] = topE2 * ft; prev[4] = topE3 * ft;
            float lE[4];
#pragma unroll
            for (int a = 0; a < 4; ++a) lE[a] = leftE[a] * fl;

            const float newCornE = prev[4];   // aligned R[i0-1][j0+3] (scale c2)

            float right[4];
            // Double-buffered E tile: issue next tile's loads before the math.
            if ((tj & 1) == 0) {
                if (tj + 1 < GT)
#pragma unroll
                    for (int a = 0; a < 4; ++a)
                        bufB[a] = *reinterpret_cast<const float4*>(
                            Eb + (size_t)(i0 + a) * NS + (j0 + 4));
                tile4w(bufA, prev, lE, right);
            } else {
                if (tj + 1 < GT)
#pragma unroll
                    for (int a = 0; a < 4; ++a)
                        bufA[a] = *reinterpret_cast<const float4*>(
                            Eb + (size_t)(i0 + a) * NS + (j0 + 4));
                tile4w(bufB, prev, lE, right);
            }

            // --- Renormalize each output group by its OWN max exponent. ---
            // Row group -> shared row frontier.
            {
                float mr = fmaxf(fmaxf(prev[1], prev[2]), fmaxf(prev[3], prev[4]));
                int emr = fexp(mr);
                float rsr = __int_as_float((127 - emr) << 23);   // 2^-emr
                float4 wrow = make_float4(prev[1] * rsr, prev[2] * rsr,
                                          prev[3] * rsr, prev[4] * rsr);
                *reinterpret_cast<float4*>(&rowE[wb][j0]) = wrow;
                rowC2[wb][tj] = (mr > 0.0f) ? (c2 + emr) : C2_NEG;
            }
            // Column group -> register left frontier for tile (ti, tj+1).
            {
                float mc = fmaxf(fmaxf(right[0], right[1]),
                                 fmaxf(right[2], right[3]));
                int emc = fexp(mc);
                float rsc = __int_as_float((127 - emc) << 23);   // 2^-emc
#pragma unroll
                for (int a = 0; a < 4; ++a) leftE[a] = right[a] * rsc;
                leftC2 = (mc > 0.0f) ? (c2 + emc) : C2_NEG;
            }
            // Corner -> own exponent (scale must TRACK its magnitude; a scale
            // derived from max() is monotone and poisons downstream alignment).
            {
                int ecn = fexp(newCornE);
                cornE  = newCornE * __int_as_float((127 - ecn) << 23);
                cornC2 = (newCornE > 0.0f) ? (c2 + ecn) : C2_NEG;
            }
        }
        __syncthreads();
    }

    // Last diagonal (kd = 254) wrote parity 0: W[N-1][N-1] = rowE[0][NS-1]*2^c2.
    if (ti == 0) {
        float e  = fmaxf(rowE[0][NS - 1], 1.1754944e-38f);  // guard (never hit)
        float c2 = (float)rowC2[0][GT - 1];
        out[b] = -(log2f(e) + c2) * 0.69314718055994530942f;
    }
}

// ---------------------------------------------------------------------------
extern "C" void kernel_launch(void* const* d_in, const int* in_sizes, int n_in,
                              void* d_out, int out_size) {
    (void)in_sizes; (void)n_in; (void)out_size;
    const float* X = (const float*)d_in[0];
    const float* Y = (const float*)d_in[1];
    float* out = (float*)d_out;

    dim3 g1(NS / 64, NS / 64, NB);   // (8, 8, 64)
    dim3 b1(16, 16);
    cdist_kernel<<<g1, b1>>>(X, Y);

    dp_kernel<<<NB, 128>>>(out);
}

// round 4
// speedup vs baseline: 2.1614x; 1.3033x over previous
#include <cuda_runtime.h>

#define NS 512       // sequence length N
#define DD 64        // feature dim d
#define NB 64        // batch B
#define GTJ 64       // column tiles (8 wide each)
#define NDIAG 192    // 128 + 64 - 1 = 191, padded even
#define C2_NEG (-0x40000000)

// 64 MB scratch: E[b,i,j] = exp(-||x_i - y_j||)
__device__ float g_E[(size_t)NB * NS * NS];

// ---------------------------------------------------------------------------
// Packed f32x2 FMA (Blackwell)
// ---------------------------------------------------------------------------
__device__ __forceinline__ void fma2(unsigned long long& d,
                                     unsigned long long a,
                                     unsigned long long b) {
    asm("fma.rn.f32x2 %0, %1, %2, %0;" : "+l"(d) : "l"(a), "l"(b));
}

// ---------------------------------------------------------------------------
// Stage 1: E[b,i,j] = exp(-sqrt(max(0, |x_i|^2 + |y_j|^2 - 2 x_i.y_j)))
// ---------------------------------------------------------------------------
__global__ void __launch_bounds__(256, 1)
cdist_kernel(const float* __restrict__ X, const float* __restrict__ Y) {
    __shared__ float Xs[64 * 64];
    __shared__ float Ys[64 * 64];
    __shared__ float xn[64], yn[64];

    const int b  = blockIdx.z;
    const int i0 = blockIdx.y * 64;
    const int j0 = blockIdx.x * 64;
    const int tid = threadIdx.y * 16 + threadIdx.x;

    const float* Xg = X + ((size_t)b * NS + i0) * DD;
    const float* Yg = Y + ((size_t)b * NS + j0) * DD;

    float4* Xs4 = reinterpret_cast<float4*>(Xs);
    float4* Ys4 = reinterpret_cast<float4*>(Ys);

#pragma unroll
    for (int t = 0; t < 4; ++t) {
        int lin = t * 256 + tid;
        int row = lin >> 4;
        int k4  = lin & 15;
        int sw  = k4 ^ (row & 15);
        Xs4[row * 16 + sw] = *reinterpret_cast<const float4*>(Xg + row * DD + k4 * 4);
        Ys4[row * 16 + sw] = *reinterpret_cast<const float4*>(Yg + row * DD + k4 * 4);
    }
    __syncthreads();

    if (tid < 128) {
        int r = tid & 63;
        const float4* P = (tid < 64) ? reinterpret_cast<const float4*>(Xs)
                                     : reinterpret_cast<const float4*>(Ys);
        float s = 0.0f;
#pragma unroll
        for (int k4 = 0; k4 < 16; ++k4) {
            float4 v = P[r * 16 + (k4 ^ (r & 15))];
            s += v.x * v.x + v.y * v.y + v.z * v.z + v.w * v.w;
        }
        if (tid < 64) xn[r] = s; else yn[r] = s;
    }
    __syncthreads();

    const int tx = threadIdx.x, ty = threadIdx.y;

    unsigned long long acc[4][4];
#pragma unroll
    for (int r = 0; r < 4; ++r)
#pragma unroll
        for (int c = 0; c < 4; ++c) acc[r][c] = 0ull;

    const ulonglong2* Xs2 = reinterpret_cast<const ulonglong2*>(Xs);
    const ulonglong2* Ys2 = reinterpret_cast<const ulonglong2*>(Ys);

#pragma unroll
    for (int k4 = 0; k4 < 16; ++k4) {
        ulonglong2 av[4], bv[4];
#pragma unroll
        for (int r = 0; r < 4; ++r) {
            int i = ty + 16 * r;
            av[r] = Xs2[i * 16 + (k4 ^ (i & 15))];
        }
#pragma unroll
        for (int c = 0; c < 4; ++c) {
            int j = tx + 16 * c;
            bv[c] = Ys2[j * 16 + (k4 ^ (j & 15))];
        }
#pragma unroll
        for (int r = 0; r < 4; ++r)
#pragma unroll
            for (int c = 0; c < 4; ++c) {
                fma2(acc[r][c], av[r].x, bv[c].x);
                fma2(acc[r][c], av[r].y, bv[c].y);
            }
    }

    float* Eout = g_E + (size_t)b * NS * NS;
#pragma unroll
    for (int r = 0; r < 4; ++r) {
        int i = ty + 16 * r;
#pragma unroll
        for (int c = 0; c < 4; ++c) {
            int j = tx + 16 * c;
            float lo = __uint_as_float((unsigned)(acc[r][c] & 0xffffffffull));
            float hi = __uint_as_float((unsigned)(acc[r][c] >> 32));
            float d2 = xn[i] + yn[j] - 2.0f * (lo + hi);
            float dist = sqrtf(fmaxf(d2, 0.0f));
            Eout[(size_t)(i0 + i) * NS + (j0 + j)] =
                exp2f(-1.4426950408889634f * dist);
        }
    }
}

// ---------------------------------------------------------------------------
// Stage 2: weight-domain soft-DTW with binary scaling. 128 threads/CTA, each
// owns 4 DP rows; per iteration processes a 4x8 tile as two 4x4 sub-tiles
// (middle frontier in registers). Branchless wavefront: inactive threads
// compute on clamped addresses and publish to a dummy SMEM slot.
// ---------------------------------------------------------------------------
__device__ __forceinline__ float exp2i_neg(int e) {
    return (e >= -126) ? __int_as_float((e + 127) << 23) : 0.0f;
}
__device__ __forceinline__ int fexp(float m) {
    return ((__float_as_int(m) >> 23) & 0xff) - 127;
}

__device__ __forceinline__ void subtile4(
    float4 top, int sTop,
    float& cornE, int& cornC2,
    float (&left)[4], int& leftC2,
    float4 e0, float4 e1, float4 e2, float4 e3,
    float4& outB, int& outC2)
{
    int c2 = max(max(sTop, cornC2), leftC2);
    const float ft = exp2i_neg(sTop   - c2);
    const float fc = exp2i_neg(cornC2 - c2);
    const float fl = exp2i_neg(leftC2 - c2);

    float prev[5];
    prev[0] = cornE * fc;
    prev[1] = top.x * ft; prev[2] = top.y * ft;
    prev[3] = top.z * ft; prev[4] = top.w * ft;
    float lE[4] = {left[0] * fl, left[1] * fl, left[2] * fl, left[3] * fl};
    const float newCorn = prev[4];

    float4 dt[4] = {e0, e1, e2, e3};
    float right[4];
#pragma unroll
    for (int a = 0; a < 4; ++a) {
        const float dd0 = dt[a].x, dd1 = dt[a].y, dd2 = dt[a].z, dd3 = dt[a].w;
        float carry = prev[0];
        prev[0] = lE[a];
        float s;
        s = (carry + prev[1]) + prev[0]; carry = prev[1]; prev[1] = dd0 * s;
        s = (carry + prev[2]) + prev[1]; carry = prev[2]; prev[2] = dd1 * s;
        s = (carry + prev[3]) + prev[2]; carry = prev[3]; prev[3] = dd2 * s;
        s = (carry + prev[4]) + prev[3];                  prev[4] = dd3 * s;
        right[a] = prev[4];
    }

    // Renorm bottom row group.
    float mr = fmaxf(fmaxf(prev[1], prev[2]), fmaxf(prev[3], prev[4]));
    int emr = fexp(mr);
    float rsr = __int_as_float((127 - emr) << 23);
    outB = make_float4(prev[1] * rsr, prev[2] * rsr, prev[3] * rsr, prev[4] * rsr);
    outC2 = (mr > 0.0f) ? (c2 + emr) : C2_NEG;

    // Renorm right column group -> left frontier for the next sub-tile.
    float mc = fmaxf(fmaxf(right[0], right[1]), fmaxf(right[2], right[3]));
    int emc = fexp(mc);
    float rsc = __int_as_float((127 - emc) << 23);
    left[0] = right[0] * rsc; left[1] = right[1] * rsc;
    left[2] = right[2] * rsc; left[3] = right[3] * rsc;
    leftC2 = (mc > 0.0f) ? (c2 + emc) : C2_NEG;

    // Corner: own-exponent renorm (scale must track magnitude).
    int ec = fexp(newCorn);
    cornE  = newCorn * __int_as_float((127 - ec) << 23);
    cornC2 = (newCorn > 0.0f) ? (c2 + ec) : C2_NEG;
}

__device__ __forceinline__ void dp_step(
    int kd, int ti, const float* __restrict__ Erow0,
    float4 (&cb)[8], float4 (&nb)[8],
    float4 (*rowE4)[2 * GTJ + 2], int (*rowC2s)[2 * GTJ + 4],
    float (&left)[4], int& leftC2, float& cornE, int& cornC2)
{
    const int tj  = kd - ti;
    const int wb  = kd & 1, rb = wb ^ 1;
    const bool act = (unsigned)tj < (unsigned)GTJ;
    const int tjr = (tj < 0) ? 0 : (tj > GTJ - 1 ? GTJ - 1 : tj);

    // Top frontier (pre-zeroed parities provide the i = -1 boundary).
    float4 t0 = rowE4[rb][2 * tjr];
    float4 t1 = rowE4[rb][2 * tjr + 1];
    int    s0 = rowC2s[rb][2 * tjr];
    int    s1 = rowC2s[rb][2 * tjr + 1];

    // Activation reset (predicated selects, no divergence machinery).
    if (tj == 0) {
        left[0] = left[1] = left[2] = left[3] = 0.0f;
        leftC2 = C2_NEG;
        cornE  = (ti == 0) ? 1.0f : 0.0f;
        cornC2 = (ti == 0) ? 0 : C2_NEG;
    }

    // Prefetch next tile (tj+1) into the other buffer (clamped, always issued).
    {
        int tn = tj + 1;
        int cb8 = ((tn < 0) ? 0 : (tn > GTJ - 1 ? GTJ - 1 : tn)) * 8;
#pragma unroll
        for (int a = 0; a < 4; ++a) {
            nb[2 * a]     = *reinterpret_cast<const float4*>(Erow0 + a * NS + cb8);
            nb[2 * a + 1] = *reinterpret_cast<const float4*>(Erow0 + a * NS + cb8 + 4);
        }
    }

    float4 b0, b1; int c0, c1;
    subtile4(t0, s0, cornE, cornC2, left, leftC2, cb[0], cb[2], cb[4], cb[6], b0, c0);
    subtile4(t1, s1, cornE, cornC2, left, leftC2, cb[1], cb[3], cb[5], cb[7], b1, c1);

    const int ws = act ? 2 * tj : 2 * GTJ;   // dummy slot 128/129 when inactive
    rowE4[wb][ws]     = b0;
    rowE4[wb][ws + 1] = b1;
    rowC2s[wb][ws]     = c0;
    rowC2s[wb][ws + 1] = c1;
    __syncthreads();
}

__global__ void __launch_bounds__(128, 1)
dp_kernel(float* __restrict__ out) {
    const int b = blockIdx.x;
    const float* Eb = g_E + (size_t)b * NS * NS;

    __shared__ __align__(16) float4 rowE4[2][2 * GTJ + 2];   // 130 slots/parity
    __shared__ int rowC2s[2][2 * GTJ + 4];

    const int ti = threadIdx.x;
    const int i0 = ti * 4;
    const float* Erow0 = Eb + (size_t)i0 * NS;

    // Pre-zero both parities (provides i = -1 boundary row: W = 0, scale C2_NEG).
    {
        float4 z = make_float4(0.f, 0.f, 0.f, 0.f);
        float4* re = &rowE4[0][0];
        for (int s = ti; s < 2 * (2 * GTJ + 2); s += 128) re[s] = z;
        int* rc = &rowC2s[0][0];
        for (int s = ti; s < 2 * (2 * GTJ + 4); s += 128) rc[s] = C2_NEG;
    }

    float4 bufA[8], bufB[8];
#pragma unroll
    for (int a = 0; a < 8; ++a) {
        bufA[a] = make_float4(0.f, 0.f, 0.f, 0.f);
        bufB[a] = bufA[a];
    }
    // Preload tile tj=0 into bufA (only thread 0 consumes it un-refreshed).
#pragma unroll
    for (int a = 0; a < 4; ++a) {
        bufA[2 * a]     = *reinterpret_cast<const float4*>(Erow0 + a * NS);
        bufA[2 * a + 1] = *reinterpret_cast<const float4*>(Erow0 + a * NS + 4);
    }

    float left[4] = {0.f, 0.f, 0.f, 0.f};
    int leftC2 = C2_NEG;
    float cornE = 0.f;
    int cornC2 = C2_NEG;

    __syncthreads();

    for (int kd = 0; kd < NDIAG; kd += 2) {
        dp_step(kd,     ti, Erow0, bufA, bufB, rowE4, rowC2s,
                left, leftC2, cornE, cornC2);
        dp_step(kd + 1, ti, Erow0, bufB, bufA, rowE4, rowC2s,
                left, leftC2, cornE, cornC2);
    }

    // Thread 127 wrote its last tile (tj=63) at kd=190 (parity 0), slot 127.
    if (ti == 0) {
        float e  = fmaxf(rowE4[0][127].w, 1.17549435e-38f);
        float c2 = (float)rowC2s[0][127];
        out[b] = -(log2f(e) + c2) * 0.69314718055994530942f;
    }
}

// ---------------------------------------------------------------------------
extern "C" void kernel_launch(void* const* d_in, const int* in_sizes, int n_in,
                              void* d_out, int out_size) {
    (void)in_sizes; (void)n_in; (void)out_size;
    const float* X = (const float*)d_in[0];
    const float* Y = (const float*)d_in[1];
    float* out = (float*)d_out;

    dim3 g1(NS / 64, NS / 64, NB);   // (8, 8, 64)
    dim3 b1(16, 16);
    cdist_kernel<<<g1, b1>>>(X, Y);

    dp_kernel<<<NB, 128>>>(out);
}